// round 6
// baseline (speedup 1.0000x reference)
#include <cuda_runtime.h>
#include <cuda_bf16.h>
#include <cstdint>
#include <cstddef>

#define OUT_FEAT 11008
#define IN_FEAT  4096
#define HAD      128
#define NBLK     (OUT_FEAT / HAD)    // 86
#define MT_TOT   (OUT_FEAT / 16)     // 688 m16 tiles
#define KT_TOT   (IN_FEAT / 16)      // 256 k16 tiles
#define NT_TOT   (IN_FEAT / 8)       // 512 n8 tiles

// ---- fragment-packed operands (device globals: alloc-free rule) ----
__device__ uint4 g_Wf[(size_t)MT_TOT * KT_TOT * 64];   // 180 MB  A fragments
__device__ uint4 g_Bf[(size_t)NT_TOT * KT_TOT * 32];   // 67 MB   B fragments
__device__ uint4 g_Rf[64 * 64];                        // Rr^T A-fragments (64 KB)
__device__ unsigned int g_absmax_bits;

__device__ __forceinline__ void split_pack(float a, float b, uint32_t& h, uint32_t& l) {
    __nv_bfloat16 ha = __float2bfloat16_rn(a);
    __nv_bfloat16 hb = __float2bfloat16_rn(b);
    __nv_bfloat16 la = __float2bfloat16_rn(a - __bfloat162float(ha));
    __nv_bfloat16 lb = __float2bfloat16_rn(b - __bfloat162float(hb));
    h = ((uint32_t)__bfloat16_as_ushort(hb) << 16) | __bfloat16_as_ushort(ha);
    l = ((uint32_t)__bfloat16_as_ushort(lb) << 16) | __bfloat16_as_ushort(la);
}

#define MMA_BF16(c, a, b0, b1)                                                 \
    asm volatile("mma.sync.aligned.m16n8k16.row.col.f32.bf16.bf16.f32 "        \
                 "{%0,%1,%2,%3},{%4,%5,%6,%7},{%8,%9},{%0,%1,%2,%3};"          \
                 : "+f"(c[0]), "+f"(c[1]), "+f"(c[2]), "+f"(c[3])              \
                 : "r"(a.x), "r"(a.y), "r"(a.z), "r"(a.w), "r"(b0), "r"(b1))

// ---------------------------------------------------------------------------
// Kernel 0: pack Rr^T into A-fragments (hi/lo bf16), once. Also zeroes absmax.
// ---------------------------------------------------------------------------
__global__ void k_packRr(const float* __restrict__ Rr) {
    extern __shared__ float S[];   // 128 x 132
    const int tid = threadIdx.x;
    if (tid == 0) g_absmax_bits = 0u;
    #pragma unroll
    for (int j = 0; j < 64; j++) {
        int idx = tid + j * 256;
        S[(idx >> 7) * 132 + (idx & 127)] = Rr[idx];   // S[d][h]
    }
    __syncthreads();
    const int wid = tid >> 5, lane = tid & 31;
    const int r = lane >> 2, c = (lane & 3) * 2;
    #pragma unroll
    for (int t = 0; t < 8; t++) {
        int blk = wid * 8 + t;
        int mt = blk >> 3, kt = blk & 7;
        int R = mt * 16 + r;
        const float* p0 = &S[(kt * 16 + c) * 132 + R];
        const float* p1 = &S[(kt * 16 + c + 1) * 132 + R];
        uint4 hi, lo;
        split_pack(p0[0],           p1[0],           hi.x, lo.x);
        split_pack(p0[8],           p1[8],           hi.y, lo.y);
        split_pack(p0[8 * 132],     p1[8 * 132],     hi.z, lo.z);
        split_pack(p0[8 * 132 + 8], p1[8 * 132 + 8], hi.w, lo.w);
        g_Rf[blk * 64 + lane]      = hi;
        g_Rf[blk * 64 + 32 + lane] = lo;
    }
}

// ---------------------------------------------------------------------------
// Kernel 1: tensor-core rotation, product-major issue order.
// ---------------------------------------------------------------------------
#define RT_PITCH 260
#define ROT_SMEM (128 * RT_PITCH * 4 + 64 * 64 * 16)   // 198656

__global__ __launch_bounds__(512, 1) void k_rotate(const float* __restrict__ inp) {
    extern __shared__ float S[];                    // Sin[128][260]
    uint4* Rf = (uint4*)(S + 128 * RT_PITCH);
    const int tid = threadIdx.x;
    const int b = blockIdx.y, ck = blockIdx.x;

    const float4* src = (const float4*)(inp + (size_t)b * 128 * IN_FEAT + ck * 256);
    #pragma unroll
    for (int j = 0; j < 16; j++) {
        int idx = tid + j * 512;
        int d = idx >> 6, c4 = idx & 63;
        float4 v = src[(size_t)d * (IN_FEAT / 4) + c4];
        *(float4*)&S[d * RT_PITCH + c4 * 4] = v;
    }
    #pragma unroll
    for (int j = 0; j < 8; j++) {
        int idx = tid + j * 512;
        Rf[idx] = g_Rf[idx];
    }
    __syncthreads();

    const int wid = tid >> 5, lane = tid & 31;
    const int wm = wid >> 3, wn = wid & 7;
    const int q = (lane & 3) * 2;
    const int nbase = wn * 32 + (lane >> 2);

    float acc[4][4][4];
    #pragma unroll
    for (int i = 0; i < 4; i++)
        #pragma unroll
        for (int j = 0; j < 4; j++)
            #pragma unroll
            for (int k = 0; k < 4; k++) acc[i][j][k] = 0.0f;

    for (int kt = 0; kt < 8; kt++) {
        uint32_t bh[4][2], bl[4][2];
        #pragma unroll
        for (int nt = 0; nt < 4; nt++) {
            const float* pp = &S[(kt * 16 + q) * RT_PITCH + nbase + nt * 8];
            split_pack(pp[0],            pp[RT_PITCH],     bh[nt][0], bl[nt][0]);
            split_pack(pp[8 * RT_PITCH], pp[9 * RT_PITCH], bh[nt][1], bl[nt][1]);
        }
        uint4 ah[4], al[4];
        #pragma unroll
        for (int mt = 0; mt < 4; mt++)
            ah[mt] = Rf[((wm * 4 + mt) * 8 + kt) * 64 + lane];
        // product-major: hh
        #pragma unroll
        for (int mt = 0; mt < 4; mt++)
            #pragma unroll
            for (int nt = 0; nt < 4; nt++)
                MMA_BF16(acc[mt][nt], ah[mt], bh[nt][0], bh[nt][1]);
        #pragma unroll
        for (int mt = 0; mt < 4; mt++)
            al[mt] = Rf[((wm * 4 + mt) * 8 + kt) * 64 + 32 + lane];
        // hl
        #pragma unroll
        for (int mt = 0; mt < 4; mt++)
            #pragma unroll
            for (int nt = 0; nt < 4; nt++)
                MMA_BF16(acc[mt][nt], ah[mt], bl[nt][0], bl[nt][1]);
        // lh
        #pragma unroll
        for (int mt = 0; mt < 4; mt++)
            #pragma unroll
            for (int nt = 0; nt < 4; nt++)
                MMA_BF16(acc[mt][nt], al[mt], bh[nt][0], bh[nt][1]);
        // ll (keep: rotate feeds A, preserve accuracy)
        #pragma unroll
        for (int mt = 0; mt < 4; mt++)
            #pragma unroll
            for (int nt = 0; nt < 4; nt++)
                MMA_BF16(acc[mt][nt], al[mt], bl[nt][0], bl[nt][1]);
    }

    #pragma unroll
    for (int mt = 0; mt < 4; mt++) {
        #pragma unroll
        for (int u = 0; u < 2; u++) {
            float* c0 = acc[mt][u * 2];
            float* c1 = acc[mt][u * 2 + 1];
            uint4 hi, lo;
            split_pack(c0[0], c0[1], hi.x, lo.x);
            split_pack(c0[2], c0[3], hi.y, lo.y);
            split_pack(c1[0], c1[1], hi.z, lo.z);
            split_pack(c1[2], c1[3], hi.w, lo.w);
            size_t o = ((size_t)(b * 8 + wm * 4 + mt) * KT_TOT + (ck * 16 + wn * 2 + u)) * 64;
            g_Wf[o + lane]      = hi;
            g_Wf[o + 32 + lane] = lo;
        }
    }
}

// ---------------------------------------------------------------------------
// Kernel 2: pack R_left (K,N) into B fragments (n8 x k16 blocks)
// ---------------------------------------------------------------------------
__global__ __launch_bounds__(256) void k_packB(const float* __restrict__ R) {
    __shared__ float S[64][65];
    const int n0 = blockIdx.x * 64;
    const int k0 = blockIdx.y * 64;
    const int tid = threadIdx.x;

    #pragma unroll
    for (int j = 0; j < 16; j++) {
        int idx = tid + j * 256;
        int kk = idx >> 6, nn = idx & 63;
        S[kk][nn] = R[(size_t)(k0 + kk) * IN_FEAT + n0 + nn];
    }
    __syncthreads();

    const int wid  = tid >> 5;
    const int lane = tid & 31;
    const int n = lane >> 2;
    const int q = (lane & 3) * 2;
    #pragma unroll
    for (int t = 0; t < 4; t++) {
        int blk = wid * 4 + t;
        int ntl = blk >> 2, ktl = blk & 3;
        float x0 = S[ktl * 16 + q][ntl * 8 + n];
        float x1 = S[ktl * 16 + q + 1][ntl * 8 + n];
        float x2 = S[ktl * 16 + q + 8][ntl * 8 + n];
        float x3 = S[ktl * 16 + q + 9][ntl * 8 + n];
        uint4 v;
        split_pack(x0, x1, v.x, v.z);
        split_pack(x2, x3, v.y, v.w);
        size_t o = ((size_t)(blockIdx.x * 8 + ntl) * KT_TOT + (blockIdx.y * 4 + ktl)) * 32;
        g_Bf[o + lane] = v;
    }
}

// ---------------------------------------------------------------------------
// Kernel 3: main GEMM, product-major issue order.
// ---------------------------------------------------------------------------
#define CP16(dst, src) asm volatile("cp.async.cg.shared.global [%0], [%1], 16;" :: "r"(dst), "l"(src))
#define CP_COMMIT()    asm volatile("cp.async.commit_group;" ::: "memory")
#define CP_WAIT1()     asm volatile("cp.async.wait_group 1;" ::: "memory")

#define LDS128(v, a) \
    asm volatile("ld.shared.v4.b32 {%0,%1,%2,%3}, [%4];" \
        : "=r"(v.x), "=r"(v.y), "=r"(v.z), "=r"(v.w) : "r"(a))

__device__ __forceinline__ uint32_t smem_u32(const void* p) {
    uint32_t a;
    asm("{ .reg .u64 t; cvta.to.shared.u64 t, %1; cvt.u32.u64 %0, t; }" : "=r"(a) : "l"(p));
    return a;
}

#define STAGE_BYTES 32768
#define GEMM_SMEM   (3 * STAGE_BYTES)   // 96 KB

__device__ __forceinline__ void load_stage(uint32_t su, int s, int i2, int tid,
                                           const uint4* __restrict__ Wsrc,
                                           const uint4* __restrict__ Bsrc) {
    const uint32_t sb = su + s * STAGE_BYTES;
    #pragma unroll
    for (int j = 0; j < 4; j++) {           // A: 1024 uint4
        int idx = tid + j * 256;
        int kth = idx >> 9, rem = idx & 511;
        int blk = rem >> 6, w = rem & 63;
        uint32_t dst = sb + kth * 8192 + blk * 1024 + w * 16;
        const uint4* src = Wsrc + ((size_t)blk * KT_TOT + (i2 * 2 + kth)) * 64 + w;
        CP16(dst, src);
    }
    #pragma unroll
    for (int j = 0; j < 4; j++) {           // B: 1024 uint4
        int idx = tid + j * 256;
        int kth = idx >> 9, rem = idx & 511;
        int blk = rem >> 5, w = rem & 31;
        uint32_t dst = sb + 16384 + kth * 8192 + blk * 512 + w * 16;
        const uint4* src = Bsrc + ((size_t)blk * KT_TOT + (i2 * 2 + kth)) * 32 + w;
        CP16(dst, src);
    }
}

__global__ __launch_bounds__(256, 2) void k_gemm(float* __restrict__ C) {
    extern __shared__ __align__(16) uint8_t smem[];
    __shared__ float red[8];
    const uint32_t su = smem_u32(smem);

    const int tid  = threadIdx.x;
    const int wid  = tid >> 5;
    const int lane = tid & 31;
    const int wm   = wid >> 2;
    const int wn   = wid & 3;

    // grid swizzle: 8bm x 32bn supertiles for L2 reuse
    const int lin = blockIdx.x;
    const int g   = lin >> 8;
    const int r_  = lin & 255;
    const int gsz = (NBLK - g * 8 < 8) ? (NBLK - g * 8) : 8;
    const int bm  = g * 8 + r_ % gsz;
    const int bn  = r_ / gsz;

    const uint4* Wsrc = g_Wf + (size_t)(bm * 8) * KT_TOT * 64;
    const uint4* Bsrc = g_Bf + (size_t)(bn * 16) * KT_TOT * 32;

    float acc[4][4][4];
    #pragma unroll
    for (int i = 0; i < 4; i++)
        #pragma unroll
        for (int j = 0; j < 4; j++)
            #pragma unroll
            for (int k = 0; k < 4; k++) acc[i][j][k] = 0.0f;

    load_stage(su, 0, 0, tid, Wsrc, Bsrc); CP_COMMIT();
    load_stage(su, 1, 1, tid, Wsrc, Bsrc); CP_COMMIT();

    for (int i2 = 0; i2 < KT_TOT / 2; i2++) {     // 128 k32 chunks
        const int s = i2 % 3;
        CP_WAIT1();
        __syncthreads();

        const uint32_t sb = su + s * STAGE_BYTES;
        #pragma unroll
        for (int kth = 0; kth < 2; kth++) {
            const uint32_t ab = sb + kth * 8192;
            const uint32_t bb = sb + 16384 + kth * 8192;
            uint4 bf[4], ah[4], al[4];
            #pragma unroll
            for (int nt = 0; nt < 4; nt++)
                LDS128(bf[nt], bb + (wn * 4 + nt) * 512 + lane * 16);
            #pragma unroll
            for (int mt = 0; mt < 4; mt++)
                LDS128(ah[mt], ab + (wm * 4 + mt) * 1024 + lane * 16);
            // product-major: hh (16 independent accs)
            #pragma unroll
            for (int mt = 0; mt < 4; mt++)
                #pragma unroll
                for (int nt = 0; nt < 4; nt++)
                    MMA_BF16(acc[mt][nt], ah[mt], bf[nt].x, bf[nt].y);
            // al loads hidden under hh burst
            #pragma unroll
            for (int mt = 0; mt < 4; mt++)
                LDS128(al[mt], ab + (wm * 4 + mt) * 1024 + lane * 16 + 512);
            // hl
            #pragma unroll
            for (int mt = 0; mt < 4; mt++)
                #pragma unroll
                for (int nt = 0; nt < 4; nt++)
                    MMA_BF16(acc[mt][nt], ah[mt], bf[nt].z, bf[nt].w);
            // lh
            #pragma unroll
            for (int mt = 0; mt < 4; mt++)
                #pragma unroll
                for (int nt = 0; nt < 4; nt++)
                    MMA_BF16(acc[mt][nt], al[mt], bf[nt].x, bf[nt].y);
        }

        if (i2 + 2 < KT_TOT / 2)
            load_stage(su, (i2 + 2) % 3, i2 + 2, tid, Wsrc, Bsrc);
        CP_COMMIT();
    }

    // absmax
    float m = 0.0f;
    #pragma unroll
    for (int i = 0; i < 4; i++)
        #pragma unroll
        for (int j = 0; j < 4; j++)
            #pragma unroll
            for (int k = 0; k < 4; k++) m = fmaxf(m, fabsf(acc[i][j][k]));
    #pragma unroll
    for (int off = 16; off > 0; off >>= 1)
        m = fmaxf(m, __shfl_xor_sync(0xFFFFFFFFu, m, off));
    if (lane == 0) red[wid] = m;
    __syncthreads();
    if (tid == 0) {
        float mm = red[0];
        #pragma unroll
        for (int w = 1; w < 8; w++) mm = fmaxf(mm, red[w]);
        atomicMax(&g_absmax_bits, __float_as_uint(mm));
    }

    // store pre-quant Y
    const int row0 = bm * 128 + wm * 64 + (lane >> 2);
    const int col0 = bn * 128 + wn * 32 + (lane & 3) * 2;
    #pragma unroll
    for (int mt = 0; mt < 4; mt++) {
        #pragma unroll
        for (int nt = 0; nt < 4; nt++) {
            float* p0 = C + (size_t)(row0 + mt * 16) * IN_FEAT + col0 + nt * 8;
            float* p1 = C + (size_t)(row0 + mt * 16 + 8) * IN_FEAT + col0 + nt * 8;
            *(float2*)p0 = make_float2(acc[mt][nt][0], acc[mt][nt][1]);
            *(float2*)p1 = make_float2(acc[mt][nt][2], acc[mt][nt][3]);
        }
    }
}

// ---------------------------------------------------------------------------
// Kernel 4: fake-quant in place
// ---------------------------------------------------------------------------
__global__ __launch_bounds__(256) void k_quant(float* __restrict__ y) {
    const float am = __uint_as_float(g_absmax_bits);
    const float s  = fmaxf(am * (1.0f / 127.0f), 1.17549435e-38f);
    size_t idx = (size_t)blockIdx.x * blockDim.x + threadIdx.x;
    float4 v = ((const float4*)y)[idx];
    float4 r;
    r.x = fminf(fmaxf(rintf(v.x / s), -127.0f), 127.0f) * s;
    r.y = fminf(fmaxf(rintf(v.y / s), -127.0f), 127.0f) * s;
    r.z = fminf(fmaxf(rintf(v.z / s), -127.0f), 127.0f) * s;
    r.w = fminf(fmaxf(rintf(v.w / s), -127.0f), 127.0f) * s;
    ((float4*)y)[idx] = r;
}

// ---------------------------------------------------------------------------
extern "C" void kernel_launch(void* const* d_in, const int* in_sizes, int n_in,
                              void* d_out, int out_size) {
    const float* inp     = (const float*)d_in[0];   // (11008, 4096)
    const float* R_left  = (const float*)d_in[1];   // (4096, 4096)
    const float* R_right = (const float*)d_in[2];   // (128, 128)
    float* out = (float*)d_out;                     // (11008, 4096)

    const int PACKRR_SMEM = 128 * 132 * 4;          // 67584
    cudaFuncSetAttribute(k_packRr, cudaFuncAttributeMaxDynamicSharedMemorySize, PACKRR_SMEM);
    cudaFuncSetAttribute(k_rotate, cudaFuncAttributeMaxDynamicSharedMemorySize, ROT_SMEM);
    cudaFuncSetAttribute(k_gemm,   cudaFuncAttributeMaxDynamicSharedMemorySize, GEMM_SMEM);

    k_packRr<<<1, 256, PACKRR_SMEM>>>(R_right);
    k_rotate<<<dim3(IN_FEAT / 256, NBLK), 512, ROT_SMEM>>>(inp);
    k_packB<<<dim3(IN_FEAT / 64, IN_FEAT / 64), 256>>>(R_left);
    k_gemm<<<NBLK * 32, 256, GEMM_SMEM>>>(out);

    const size_t n4 = ((size_t)OUT_FEAT * IN_FEAT) / 4;
    k_quant<<<(unsigned)(n4 / 256), 256>>>(out);
}